// round 1
// baseline (speedup 1.0000x reference)
#include <cuda_runtime.h>

#define BATCH 64
#define TLEN 2048
#define JLEN 128
#define DDIM 512

#define BT 128   // t tile
#define BJ 64    // j tile
#define BK 16    // k tile
#define NKB (DDIM / BK)  // 32

// Scratch: sim[b][j][t], fp32, 64 MB
__device__ float g_sim[(size_t)BATCH * JLEN * TLEN];
__device__ float g_max[BATCH * JLEN];
__device__ float g_invden[BATCH * JLEN];

// ---------------------------------------------------------------------------
// Kernel 1: per-batch GEMM  sim[j][t] = sum_d (question[j][d]*w[d]) * context[t][d]
// Tile 64(j) x 128(t), BK=16, 256 threads, 4x8 microtile.
// Skips tiles fully outside (t >= clen) or (j >= qlen).
// ---------------------------------------------------------------------------
__global__ __launch_bounds__(256) void gemm_kernel(
    const float* __restrict__ question,
    const float* __restrict__ context,
    const int* __restrict__ qlen,
    const int* __restrict__ clen,
    const float* __restrict__ weight)
{
    const int b  = blockIdx.z;
    const int j0 = blockIdx.y * BJ;
    const int t0 = blockIdx.x * BT;
    const int cl = clen[b];
    const int ql = qlen[b];
    if (t0 >= cl || j0 >= ql) return;

    __shared__ float As[BK][BJ + 4];   // [k][j], row stride 68 floats (16B aligned)
    __shared__ float Bs[BK][BT + 4];   // [k][t], row stride 132 floats (16B aligned)
    __shared__ float ws[DDIM];

    const int tid = threadIdx.x;

    // stage weight vector
    for (int i = tid; i < DDIM; i += 256) ws[i] = weight[i];
    __syncthreads();

    // global load assignments
    const int arow = tid >> 2;          // 0..63  (j within tile)
    const int acol = (tid & 3) << 2;    // 0,4,8,12 (k within tile)
    const int brow = tid >> 1;          // 0..127 (t within tile)
    const int bcol = (tid & 1) << 3;    // 0,8    (k within tile)

    const float* Aptr = question + ((size_t)(b * JLEN + j0 + arow) * DDIM) + acol;
    const float* Bptr = context  + ((size_t)(b * TLEN + t0 + brow) * DDIM) + bcol;

    // preload tile 0
    {
        float4 av  = *reinterpret_cast<const float4*>(Aptr);
        float4 bv0 = *reinterpret_cast<const float4*>(Bptr);
        float4 bv1 = *reinterpret_cast<const float4*>(Bptr + 4);
        As[acol + 0][arow] = av.x * ws[acol + 0];
        As[acol + 1][arow] = av.y * ws[acol + 1];
        As[acol + 2][arow] = av.z * ws[acol + 2];
        As[acol + 3][arow] = av.w * ws[acol + 3];
        Bs[bcol + 0][brow] = bv0.x;
        Bs[bcol + 1][brow] = bv0.y;
        Bs[bcol + 2][brow] = bv0.z;
        Bs[bcol + 3][brow] = bv0.w;
        Bs[bcol + 4][brow] = bv1.x;
        Bs[bcol + 5][brow] = bv1.y;
        Bs[bcol + 6][brow] = bv1.z;
        Bs[bcol + 7][brow] = bv1.w;
    }
    __syncthreads();

    const int ty = tid >> 4;   // 0..15 -> j_sub = ty*4
    const int tx = tid & 15;   // 0..15 -> t_sub = tx*8

    float acc[4][8];
    #pragma unroll
    for (int i = 0; i < 4; ++i)
        #pragma unroll
        for (int c = 0; c < 8; ++c) acc[i][c] = 0.0f;

    for (int kb = 0; kb < NKB; ++kb) {
        float4 nav, nbv0, nbv1;
        const bool more = (kb + 1 < NKB);
        if (more) {
            nav  = *reinterpret_cast<const float4*>(Aptr + (kb + 1) * BK);
            nbv0 = *reinterpret_cast<const float4*>(Bptr + (kb + 1) * BK);
            nbv1 = *reinterpret_cast<const float4*>(Bptr + (kb + 1) * BK + 4);
        }

        #pragma unroll
        for (int kk = 0; kk < BK; ++kk) {
            const float4 a = *reinterpret_cast<const float4*>(&As[kk][ty << 2]);
            const float4 p = *reinterpret_cast<const float4*>(&Bs[kk][tx << 3]);
            const float4 q = *reinterpret_cast<const float4*>(&Bs[kk][(tx << 3) + 4]);
            const float av4[4] = {a.x, a.y, a.z, a.w};
            const float bv8[8] = {p.x, p.y, p.z, p.w, q.x, q.y, q.z, q.w};
            #pragma unroll
            for (int i = 0; i < 4; ++i)
                #pragma unroll
                for (int c = 0; c < 8; ++c)
                    acc[i][c] += av4[i] * bv8[c];
        }

        if (more) {
            __syncthreads();
            const int kb1 = (kb + 1) * BK;
            As[acol + 0][arow] = nav.x * ws[kb1 + acol + 0];
            As[acol + 1][arow] = nav.y * ws[kb1 + acol + 1];
            As[acol + 2][arow] = nav.z * ws[kb1 + acol + 2];
            As[acol + 3][arow] = nav.w * ws[kb1 + acol + 3];
            Bs[bcol + 0][brow] = nbv0.x;
            Bs[bcol + 1][brow] = nbv0.y;
            Bs[bcol + 2][brow] = nbv0.z;
            Bs[bcol + 3][brow] = nbv0.w;
            Bs[bcol + 4][brow] = nbv1.x;
            Bs[bcol + 5][brow] = nbv1.y;
            Bs[bcol + 6][brow] = nbv1.z;
            Bs[bcol + 7][brow] = nbv1.w;
            __syncthreads();
        }
    }

    // epilogue: sim[b][j0+ty*4+i][t0+tx*8 + 0..7]
    #pragma unroll
    for (int i = 0; i < 4; ++i) {
        float* row = g_sim + ((size_t)(b * JLEN + j0 + (ty << 2) + i)) * TLEN + t0 + (tx << 3);
        float4 lo = make_float4(acc[i][0], acc[i][1], acc[i][2], acc[i][3]);
        float4 hi = make_float4(acc[i][4], acc[i][5], acc[i][6], acc[i][7]);
        *reinterpret_cast<float4*>(row)     = lo;
        *reinterpret_cast<float4*>(row + 4) = hi;
    }
}

// ---------------------------------------------------------------------------
// Kernel 2: per (b, j<qlen): max over t<clen, then sum of exp, store max & 1/sum
// ---------------------------------------------------------------------------
__device__ __forceinline__ float warpMax(float v) {
    #pragma unroll
    for (int o = 16; o > 0; o >>= 1) v = fmaxf(v, __shfl_xor_sync(0xffffffffu, v, o));
    return v;
}
__device__ __forceinline__ float warpSum(float v) {
    #pragma unroll
    for (int o = 16; o > 0; o >>= 1) v += __shfl_xor_sync(0xffffffffu, v, o);
    return v;
}

__global__ __launch_bounds__(256) void stats_kernel(
    const int* __restrict__ qlen,
    const int* __restrict__ clen)
{
    const int b = blockIdx.y;
    const int j = blockIdx.x;
    if (j >= qlen[b]) return;
    const int cl = clen[b];

    const float* row = g_sim + ((size_t)(b * JLEN + j)) * TLEN;
    const int tid = threadIdx.x;

    __shared__ float red[8];
    __shared__ float smax;

    float m = -3.4028235e38f;
    for (int t = tid; t < cl; t += 256) m = fmaxf(m, row[t]);
    m = warpMax(m);
    if ((tid & 31) == 0) red[tid >> 5] = m;
    __syncthreads();
    if (tid == 0) {
        float mm = red[0];
        #pragma unroll
        for (int i = 1; i < 8; ++i) mm = fmaxf(mm, red[i]);
        smax = mm;
    }
    __syncthreads();
    m = smax;

    float s = 0.0f;
    for (int t = tid; t < cl; t += 256) s += __expf(row[t] - m);
    s = warpSum(s);
    if ((tid & 31) == 0) red[tid >> 5] = s;
    __syncthreads();
    if (tid == 0) {
        float ss = 0.0f;
        #pragma unroll
        for (int i = 0; i < 8; ++i) ss += red[i];
        g_max[b * JLEN + j]    = m;
        g_invden[b * JLEN + j] = 1.0f / ss;
    }
}

// ---------------------------------------------------------------------------
// Kernel 3: out[b,t] = sum_{j<qlen} exp(sim[b][j][t]-max)*invden  (t<clen), else 0
// ---------------------------------------------------------------------------
__global__ __launch_bounds__(256) void out_kernel(
    const int* __restrict__ qlen,
    const int* __restrict__ clen,
    float* __restrict__ out)
{
    const int b = blockIdx.y;
    const int t = blockIdx.x * 256 + threadIdx.x;
    const int ql = qlen[b];
    const int cl = clen[b];

    __shared__ float sm[JLEN];
    __shared__ float sd[JLEN];
    for (int jj = threadIdx.x; jj < ql; jj += 256) {
        sm[jj] = g_max[b * JLEN + jj];
        sd[jj] = g_invden[b * JLEN + jj];
    }
    __syncthreads();

    float r = 0.0f;
    if (t < cl) {
        const float* col = g_sim + (size_t)b * JLEN * TLEN + t;
        #pragma unroll 4
        for (int jj = 0; jj < ql; ++jj)
            r += __expf(col[(size_t)jj * TLEN] - sm[jj]) * sd[jj];
    }
    out[b * TLEN + t] = r;
}

// ---------------------------------------------------------------------------
extern "C" void kernel_launch(void* const* d_in, const int* in_sizes, int n_in,
                              void* d_out, int out_size)
{
    const float* question = (const float*)d_in[0];
    const float* context  = (const float*)d_in[1];
    const int*   qlen     = (const int*)d_in[2];
    const int*   clen     = (const int*)d_in[3];
    const float* weight   = (const float*)d_in[4];
    float* out = (float*)d_out;

    dim3 g1(TLEN / BT, JLEN / BJ, BATCH);   // 16 x 2 x 64
    gemm_kernel<<<g1, 256>>>(question, context, qlen, clen, weight);

    dim3 g2(JLEN, BATCH);                   // 128 x 64
    stats_kernel<<<g2, 256>>>(qlen, clen);

    dim3 g3(TLEN / 256, BATCH);             // 8 x 64
    out_kernel<<<g3, 256>>>(qlen, clen, out);
}